// round 16
// baseline (speedup 1.0000x reference)
#include <cuda_runtime.h>
#include <cuda_fp16.h>
#include <stdint.h>
#include <math.h>

// Problem constants
#define Bb   2
#define SS   2048
#define DD   2048
#define HH   16
#define HD   128
#define MTOT 4096   // Bb*SS
#define KK   2048

// ---------------------------------------------------------------------------
// Scratch (device globals: allocation-free rule)
// ---------------------------------------------------------------------------
__device__ __half g_x16[(size_t)MTOT * DD];
__device__ __half g_w16[(size_t)4 * DD * DD];   // Wq,Wk,Wv,Wo (fp16)
__device__ __half g_q16[(size_t)Bb * HH * SS * HD];  // [b,h,s,hd]
__device__ __half g_k16[(size_t)Bb * HH * SS * HD];
__device__ __half g_v16[(size_t)Bb * HH * SS * HD];
__device__ __half g_a16[(size_t)MTOT * DD];     // attn out [b,s,d]

// ---------------------------------------------------------------------------
// PTX helpers (family-safe: sm_80-class instructions only)
// ---------------------------------------------------------------------------
__device__ __forceinline__ uint32_t smem_to_u32(const void* p) {
    uint32_t a;
    asm("{ .reg .u64 t; cvta.to.shared.u64 t, %1; cvt.u32.u64 %0, t; }"
        : "=r"(a) : "l"(p));
    return a;
}

__device__ __forceinline__ void cp_async16(uint32_t saddr, const void* gaddr) {
    asm volatile("cp.async.cg.shared.global [%0], [%1], 16;"
                 :: "r"(saddr), "l"(gaddr) : "memory");
}
#define CP_COMMIT() asm volatile("cp.async.commit_group;" ::: "memory")
#define CP_WAIT1()  asm volatile("cp.async.wait_group 1;" ::: "memory")

#define LDSM4(r0, r1, r2, r3, addr) \
    asm volatile("ldmatrix.sync.aligned.m8n8.x4.shared.b16 {%0,%1,%2,%3}, [%4];" \
                 : "=r"(r0), "=r"(r1), "=r"(r2), "=r"(r3) : "r"(addr))

#define LDSM4T(r0, r1, r2, r3, addr) \
    asm volatile("ldmatrix.sync.aligned.m8n8.x4.trans.shared.b16 {%0,%1,%2,%3}, [%4];" \
                 : "=r"(r0), "=r"(r1), "=r"(r2), "=r"(r3) : "r"(addr))

#define MMAF16(d, a, b) \
    asm volatile("mma.sync.aligned.m16n8k16.row.col.f32.f16.f16.f32 " \
                 "{%0,%1,%2,%3}, {%4,%5,%6,%7}, {%8,%9}, {%0,%1,%2,%3};" \
                 : "+f"((d)[0]), "+f"((d)[1]), "+f"((d)[2]), "+f"((d)[3]) \
                 : "r"((a)[0]), "r"((a)[1]), "r"((a)[2]), "r"((a)[3]), \
                   "r"((b)[0]), "r"((b)[1]))

__device__ __forceinline__ uint32_t packh2f(float a, float b) {
    __half2 t = __floats2half2_rn(a, b);
    return *(uint32_t*)&t;
}

// ---------------------------------------------------------------------------
// Fused convert: x and all 4 weights -> fp16.  blockIdx.y: 0 -> x, 1..4 -> W.
// ---------------------------------------------------------------------------
__global__ __launch_bounds__(256) void split_all_kernel(
    const float* __restrict__ x,  const float* __restrict__ Wq,
    const float* __restrict__ Wk, const float* __restrict__ Wv,
    const float* __restrict__ Wo,
    __half* __restrict__ x16, __half* __restrict__ w16,
    int xn4, int wn4)
{
    const int y = blockIdx.y;
    const float* in;
    __half* h16;
    int n4;
    if (y == 0) { in = x; h16 = x16; n4 = xn4; }
    else {
        const float* ws[4] = {Wq, Wk, Wv, Wo};
        in = ws[y - 1];
        h16 = w16 + (size_t)(y - 1) * DD * DD;
        n4 = wn4;
    }
    int i = blockIdx.x * blockDim.x + threadIdx.x;
    if (i >= n4) return;
    float4 v = ((const float4*)in)[i];
    ((uint32_t*)h16)[2 * i + 0] = packh2f(v.x, v.y);
    ((uint32_t*)h16)[2 * i + 1] = packh2f(v.z, v.w);
}

// ---------------------------------------------------------------------------
// fp16 single-term GEMM:  Y[m,n] = sum_k X16[m,k] * W16[n,k]
// 512 threads / 16 warps, warp tile 32x32, CTA 128x128.
// BK=128 (8 k16 steps per chunk), 3-stage cp.async ring, one barrier/chunk:
//   wait1 -> sync -> load slot (t+2)%3 (its readers finished pre-sync) -> mma.
// SMEM row: 256B data + 16B pad (pitch 272 -> conflict-free ldmatrix,
// same layout proven in attention).
// qkv==1: gridDim.z selects weight slice; fp16 Q/K/V out in [b,h,s,hd].
// qkv==0: fp32 output Yf.
// ---------------------------------------------------------------------------
#define TPITCHB  272
#define TILEB    (128 * TPITCHB)       // 34816
#define STAGEB   (2 * TILEB)           // 69632 (X tile + W tile)
#define NSTAGE   3
#define GSMEM_TOTAL (NSTAGE * STAGEB)  // 208896
#define NCHUNK   (KK / 128)            // 16

__global__ __launch_bounds__(512, 1) void gemm_f16(
    const __half* __restrict__ X16, const __half* __restrict__ W16Base,
    float* __restrict__ Yf,
    __half* __restrict__ Y0, __half* __restrict__ Y1, __half* __restrict__ Y2,
    int qkv)
{
    extern __shared__ char smem[];
    const uint32_t sb = smem_to_u32(smem);

    const int tid  = threadIdx.x;
    const int wid  = tid >> 5;
    const int lane = tid & 31;
    const int wm   = wid >> 2;    // 0..3
    const int wn   = wid & 3;     // 0..3
    const int m0   = blockIdx.y * 128;
    const int n0   = blockIdx.x * 128;
    const int z    = blockIdx.z;

    const __half* W16 = W16Base + (size_t)z * DD * DD;

    // loader: 2 groups of 256 threads (tile 0: X, tile 1: W).
    // Per stage/tile: 128 rows x 16 segs = 2048 cp.async -> 8 per thread.
    const int ltile = tid >> 8;
    const int lwi   = tid & 255;
    const __half* gbase = (ltile == 0) ? X16 : W16;
    const int rowoff = (ltile == 0) ? m0 : n0;
    const uint32_t stile = sb + ltile * TILEB;

    auto load_stage = [&](int chunk, int s) {
        const int k0 = chunk * 128;
        const uint32_t sstage = stile + s * STAGEB;
        #pragma unroll
        for (int i = 0; i < 8; i++) {
            int idx = lwi + i * 256;
            int row = idx >> 4;
            int seg = idx & 15;
            cp_async16(sstage + (uint32_t)(row * TPITCHB + seg * 16),
                       gbase + (size_t)(rowoff + row) * KK + k0 + seg * 8);
        }
    };

    const uint32_t aoff = (uint32_t)((wm * 32 + (lane & 15)) * TPITCHB + (lane >> 4) * 16);
    const uint32_t boff = (uint32_t)((wn * 32 + ((lane >> 4) << 3) + (lane & 7)) * TPITCHB
                                     + ((lane >> 3) & 1) * 16);

    float acc[2][4][4];
    #pragma unroll
    for (int mt = 0; mt < 2; mt++)
        #pragma unroll
        for (int nt = 0; nt < 4; nt++)
            #pragma unroll
            for (int r = 0; r < 4; r++) acc[mt][nt][r] = 0.f;

    load_stage(0, 0); CP_COMMIT();
    load_stage(1, 1); CP_COMMIT();

    for (int t = 0; t < NCHUNK; t++) {
        const int s = t % NSTAGE;
        CP_WAIT1();            // chunk t resident (t+1 may be in flight)
        __syncthreads();       // all warps finished chunk t-1 -> slot (t+2)%3 free

        if (t + 2 < NCHUNK) load_stage(t + 2, (t + 2) % NSTAGE);
        CP_COMMIT();

        const uint32_t stA = sb + s * STAGEB;
        const uint32_t stB = stA + TILEB;

        #pragma unroll
        for (int ks = 0; ks < 8; ks++) {
            uint32_t ah[2][4], bh[4][2];
            #pragma unroll
            for (int mt = 0; mt < 2; mt++)
                LDSM4(ah[mt][0], ah[mt][1], ah[mt][2], ah[mt][3],
                      stA + aoff + mt * (16 * TPITCHB) + ks * 32);
            #pragma unroll
            for (int bt = 0; bt < 2; bt++) {
                uint32_t r0, r1, r2, r3;
                LDSM4(r0, r1, r2, r3, stB + boff + bt * (16 * TPITCHB) + ks * 32);
                bh[bt * 2][0] = r0; bh[bt * 2][1] = r1;
                bh[bt * 2 + 1][0] = r2; bh[bt * 2 + 1][1] = r3;
            }
            #pragma unroll
            for (int mt = 0; mt < 2; mt++)
                #pragma unroll
                for (int nt = 0; nt < 4; nt++)
                    MMAF16(acc[mt][nt], ah[mt], bh[nt]);
        }
    }

    // ---- epilogue ----
    __half* Yh = (z == 0) ? Y0 : (z == 1) ? Y1 : Y2;
    #pragma unroll
    for (int mt = 0; mt < 2; mt++) {
        const int mrow = m0 + wm * 32 + mt * 16 + (lane >> 2);
        #pragma unroll
        for (int nt = 0; nt < 4; nt++) {
            const int ncl = wn * 32 + nt * 8 + (lane & 3) * 2;
            float a0 = acc[mt][nt][0], a1 = acc[mt][nt][1];
            float a2 = acc[mt][nt][2], a3 = acc[mt][nt][3];
            if (qkv) {
                const int b = mrow >> 11;
                const int srow = mrow & 2047;
                const int h = n0 >> 7;
                size_t idx0 = (((size_t)(b * HH + h) * SS) + srow) * HD + ncl;
                size_t idx1 = idx0 + (size_t)8 * HD;
                *(uint32_t*)(Yh + idx0) = packh2f(a0, a1);
                *(uint32_t*)(Yh + idx1) = packh2f(a2, a3);
            } else {
                float* basep = Yf + (size_t)mrow * DD + n0 + ncl;
                *(float2*)basep = make_float2(a0, a1);
                *(float2*)(basep + (size_t)8 * DD) = make_float2(a2, a3);
            }
        }
    }
}

// ---------------------------------------------------------------------------
// fp16 flash attention (Round-15 proven): BQ=128, 8 warps, warp-local
// softmax, P in registers. KV stage = 128 rows (K0|V0|K1|V1), two 64-row
// halves per barrier pair. 2-stage pipeline, double-barrier structure.
// ---------------------------------------------------------------------------
#define APITCH    272
#define AQ_TILE   (128 * APITCH)     // 34816
#define AKV_TILE  (64 * APITCH)      // 17408
#define ASTAGE2   (4 * AKV_TILE)     // 69632 (K0,V0,K1,V1)
#define AOFF_STAGE AQ_TILE
#define ATT_SMEM  (AQ_TILE + 2 * ASTAGE2)   // 174080
#define NKV2      (SS / 128)         // 16

__global__ __launch_bounds__(256, 1) void attn_f16(
    const __half* __restrict__ Q16, const __half* __restrict__ K16,
    const __half* __restrict__ V16, __half* __restrict__ A16)
{
    extern __shared__ char smem[];
    const uint32_t sb = smem_to_u32(smem);

    const int tid  = threadIdx.x;
    const int wid  = tid >> 5;     // 0..7: q-row band of 16
    const int lane = tid & 31;
    const int q0   = blockIdx.x * 128;
    const int bh   = blockIdx.y;
    const size_t bhoff = (size_t)bh * SS * HD;

    // ---- load Q: 128 rows x 128 cols fp16 ----
    {
        const __half* qp = Q16 + bhoff + (size_t)q0 * HD;
        for (int i = tid; i < 128 * 16; i += 256) {
            int r = i >> 4, c = i & 15;
            *(uint4*)(smem + r * APITCH + c * 16) =
                *(const uint4*)(qp + (size_t)r * HD + c * 8);
        }
    }

    const __half* kvbase[2] = {K16 + bhoff, V16 + bhoff};
    // Stage layout: tile tau 0..3 = K_half0, V_half0, K_half1, V_half1
    auto load_kv = [&](int chunk, int s) {
        const uint32_t sstage = sb + AOFF_STAGE + s * ASTAGE2;
        #pragma unroll
        for (int t = 0; t < 16; t++) {
            int tau  = t >> 2;
            int sub  = t & 3;
            int r    = sub * 16 + (tid >> 4);   // 0..63
            int c    = tid & 15;
            int kind = tau & 1;                 // 0:K 1:V
            int half = tau >> 1;                // 0,1
            cp_async16(sstage + tau * AKV_TILE + r * APITCH + c * 16,
                       kvbase[kind] + (size_t)(chunk * 128 + half * 64 + r) * HD + c * 8);
        }
    };

    const uint32_t qBase = sb + (wid * 16 + (lane & 15)) * APITCH + (lane >> 4) * 16;
    const uint32_t kFragOff = (uint32_t)((((lane >> 4) << 3) + (lane & 7)) * APITCH
                                         + ((lane >> 3) & 1) * 16);
    const int vRow = ((lane >> 3) & 1) * 8 + (lane & 7);
    const uint32_t vColBase = (uint32_t)((lane >> 4) * 16);

    float of[16][4];
    #pragma unroll
    for (int i = 0; i < 16; i++)
        #pragma unroll
        for (int j = 0; j < 4; j++) of[i][j] = 0.f;
    float m0 = -1e30f, m1 = -1e30f, l0 = 0.f, l1 = 0.f;

    const float sm_scale = 0.08838834764831843f;  // 1/sqrt(128)

    load_kv(0, 0); CP_COMMIT();
    load_kv(1, 1); CP_COMMIT();

    for (int t = 0; t < NKV2; t++) {
        const int s = t & 1;
        CP_WAIT1();
        __syncthreads();   // stage t resident (+ Q on first iter)

        const uint32_t sstage = sb + AOFF_STAGE + s * ASTAGE2;

        #pragma unroll
        for (int h2 = 0; h2 < 2; h2++) {
            const uint32_t sK = sstage + (2 * h2) * AKV_TILE;
            const uint32_t sV = sK + AKV_TILE;

            // ---- S = Q K^T over 64 kv rows (8 n8 tiles) ----
            float sf[8][4];
            #pragma unroll
            for (int nt = 0; nt < 8; nt++)
                #pragma unroll
                for (int j = 0; j < 4; j++) sf[nt][j] = 0.f;

            #pragma unroll
            for (int ks = 0; ks < 8; ks++) {
                uint32_t qh[4], kh[8][2];
                LDSM4(qh[0], qh[1], qh[2], qh[3], qBase + ks * 32);
                #pragma unroll
                for (int nk = 0; nk < 4; nk++) {
                    uint32_t r0, r1, r2, r3;
                    LDSM4(r0, r1, r2, r3, sK + nk * (16 * APITCH) + kFragOff + ks * 32);
                    kh[nk * 2][0] = r0; kh[nk * 2][1] = r1;
                    kh[nk * 2 + 1][0] = r2; kh[nk * 2 + 1][1] = r3;
                }
                #pragma unroll
                for (int nt = 0; nt < 8; nt++)
                    MMAF16(sf[nt], qh, kh[nt]);
            }

            // ---- warp-local online softmax ----
            #pragma unroll
            for (int nt = 0; nt < 8; nt++)
                #pragma unroll
                for (int j = 0; j < 4; j++) sf[nt][j] *= sm_scale;

            float mx0 = -1e30f, mx1 = -1e30f;
            #pragma unroll
            for (int nt = 0; nt < 8; nt++) {
                mx0 = fmaxf(mx0, fmaxf(sf[nt][0], sf[nt][1]));
                mx1 = fmaxf(mx1, fmaxf(sf[nt][2], sf[nt][3]));
            }
            mx0 = fmaxf(mx0, __shfl_xor_sync(0xffffffffu, mx0, 1));
            mx0 = fmaxf(mx0, __shfl_xor_sync(0xffffffffu, mx0, 2));
            mx1 = fmaxf(mx1, __shfl_xor_sync(0xffffffffu, mx1, 1));
            mx1 = fmaxf(mx1, __shfl_xor_sync(0xffffffffu, mx1, 2));

            const float mn0 = fmaxf(m0, mx0);
            const float mn1 = fmaxf(m1, mx1);
            const float al0 = __expf(m0 - mn0);
            const float al1 = __expf(m1 - mn1);

            float sum0 = 0.f, sum1 = 0.f;
            #pragma unroll
            for (int nt = 0; nt < 8; nt++) {
                sf[nt][0] = __expf(sf[nt][0] - mn0);
                sf[nt][1] = __expf(sf[nt][1] - mn0);
                sf[nt][2] = __expf(sf[nt][2] - mn1);
                sf[nt][3] = __expf(sf[nt][3] - mn1);
                sum0 += sf[nt][0] + sf[nt][1];
                sum1 += sf[nt][2] + sf[nt][3];
            }
            sum0 += __shfl_xor_sync(0xffffffffu, sum0, 1);
            sum0 += __shfl_xor_sync(0xffffffffu, sum0, 2);
            sum1 += __shfl_xor_sync(0xffffffffu, sum1, 1);
            sum1 += __shfl_xor_sync(0xffffffffu, sum1, 2);

            l0 = l0 * al0 + sum0;
            l1 = l1 * al1 + sum1;
            m0 = mn0; m1 = mn1;

            #pragma unroll
            for (int nt = 0; nt < 16; nt++) {
                of[nt][0] *= al0; of[nt][1] *= al0;
                of[nt][2] *= al1; of[nt][3] *= al1;
            }

            // ---- O += P V  (P fp16 from registers) ----
            #pragma unroll
            for (int ks = 0; ks < 4; ks++) {
                const int t0 = 2 * ks, t1 = 2 * ks + 1;
                uint32_t ph[4];
                ph[0] = packh2f(sf[t0][0], sf[t0][1]);
                ph[1] = packh2f(sf[t0][2], sf[t0][3]);
                ph[2] = packh2f(sf[t1][0], sf[t1][1]);
                ph[3] = packh2f(sf[t1][2], sf[t1][3]);
                const uint32_t vro = (uint32_t)((ks * 16 + vRow) * APITCH) + vColBase;
                #pragma unroll
                for (int nt4 = 0; nt4 < 8; nt4++) {
                    uint32_t r0, r1, r2, r3;
                    uint32_t vh0[2], vh1[2];
                    LDSM4T(r0, r1, r2, r3, sV + vro + nt4 * 32);
                    vh0[0] = r0; vh0[1] = r1; vh1[0] = r2; vh1[1] = r3;
                    MMAF16(of[nt4 * 2], ph, vh0);
                    MMAF16(of[nt4 * 2 + 1], ph, vh1);
                }
            }
        }

        __syncthreads();   // all reads of stage s done before overwrite
        if (t + 2 < NKV2) { load_kv(t + 2, s); CP_COMMIT(); }
    }

    // ---- epilogue: O/l -> fp16 at [b, s, d] ----
    const int b = bh >> 4;
    const int h = bh & 15;
    const float inv0 = 1.0f / l0;
    const float inv1 = 1.0f / l1;
    const int s0 = q0 + wid * 16 + (lane >> 2);
    #pragma unroll
    for (int nt = 0; nt < 16; nt++) {
        const int d = h * 128 + nt * 8 + (lane & 3) * 2;
        size_t idx0 = ((size_t)(b * SS + s0)) * DD + d;
        size_t idx1 = idx0 + (size_t)8 * DD;
        *(uint32_t*)(A16 + idx0) = packh2f(of[nt][0] * inv0, of[nt][1] * inv0);
        *(uint32_t*)(A16 + idx1) = packh2f(of[nt][2] * inv1, of[nt][3] * inv1);
    }
}

// ---------------------------------------------------------------------------
extern "C" void kernel_launch(void* const* d_in, const int* in_sizes, int n_in,
                              void* d_out, int out_size)
{
    const float* x  = (const float*)d_in[0];
    const float* Wq = (const float*)d_in[1];
    const float* Wk = (const float*)d_in[2];
    const float* Wv = (const float*)d_in[3];
    const float* Wo = (const float*)d_in[4];

    __half *x16, *w16, *q16, *k16, *v16, *a16;
    cudaGetSymbolAddress((void**)&x16, g_x16);
    cudaGetSymbolAddress((void**)&w16, g_w16);
    cudaGetSymbolAddress((void**)&q16, g_q16);
    cudaGetSymbolAddress((void**)&k16, g_k16);
    cudaGetSymbolAddress((void**)&v16, g_v16);
    cudaGetSymbolAddress((void**)&a16, g_a16);

    cudaFuncSetAttribute(gemm_f16, cudaFuncAttributeMaxDynamicSharedMemorySize,
                         GSMEM_TOTAL);
    cudaFuncSetAttribute(attn_f16, cudaFuncAttributeMaxDynamicSharedMemorySize,
                         ATT_SMEM);

    const int xn4 = (int)((size_t)MTOT * DD / 4);
    const int wn4 = (int)((size_t)DD * DD / 4);

    split_all_kernel<<<dim3((xn4 + 255) / 256, 5), 256>>>(
        x, Wq, Wk, Wv, Wo, x16, w16, xn4, wn4);

    dim3 gqkv(DD / 128, MTOT / 128, 3);
    gemm_f16<<<gqkv, 512, GSMEM_TOTAL>>>(x16, w16, nullptr,
                                         q16, k16, v16, 1);

    attn_f16<<<dim3(SS / 128, Bb * HH), 256, ATT_SMEM>>>(q16, k16, v16, a16);

    dim3 go(DD / 128, MTOT / 128, 1);
    gemm_f16<<<go, 512, GSMEM_TOTAL>>>(a16, w16 + (size_t)3 * DD * DD,
                                       (float*)d_out,
                                       nullptr, nullptr, nullptr, 0);
}

// round 17
// speedup vs baseline: 1.0241x; 1.0241x over previous
#include <cuda_runtime.h>
#include <cuda_fp16.h>
#include <stdint.h>
#include <math.h>

// Problem constants
#define Bb   2
#define SS   2048
#define DD   2048
#define HH   16
#define HD   128
#define MTOT 4096   // Bb*SS
#define KK   2048

// ---------------------------------------------------------------------------
// Scratch (device globals: allocation-free rule)
// ---------------------------------------------------------------------------
__device__ __half g_x16[(size_t)MTOT * DD];
__device__ __half g_w16[(size_t)4 * DD * DD];   // Wq,Wk,Wv,Wo (fp16)
__device__ __half g_q16[(size_t)Bb * HH * SS * HD];  // [b,h,s,hd]
__device__ __half g_k16[(size_t)Bb * HH * SS * HD];
__device__ __half g_v16[(size_t)Bb * HH * SS * HD];
__device__ __half g_a16[(size_t)MTOT * DD];     // attn out [b,s,d]

// ---------------------------------------------------------------------------
// PTX helpers (family-safe: sm_80-class instructions only)
// ---------------------------------------------------------------------------
__device__ __forceinline__ uint32_t smem_to_u32(const void* p) {
    uint32_t a;
    asm("{ .reg .u64 t; cvta.to.shared.u64 t, %1; cvt.u32.u64 %0, t; }"
        : "=r"(a) : "l"(p));
    return a;
}

__device__ __forceinline__ void cp_async16(uint32_t saddr, const void* gaddr) {
    asm volatile("cp.async.cg.shared.global [%0], [%1], 16;"
                 :: "r"(saddr), "l"(gaddr) : "memory");
}
#define CP_COMMIT() asm volatile("cp.async.commit_group;" ::: "memory")
#define CP_WAIT1()  asm volatile("cp.async.wait_group 1;" ::: "memory")
#define CP_WAIT2()  asm volatile("cp.async.wait_group 2;" ::: "memory")

#define LDSM4(r0, r1, r2, r3, addr) \
    asm volatile("ldmatrix.sync.aligned.m8n8.x4.shared.b16 {%0,%1,%2,%3}, [%4];" \
                 : "=r"(r0), "=r"(r1), "=r"(r2), "=r"(r3) : "r"(addr))

#define LDSM4T(r0, r1, r2, r3, addr) \
    asm volatile("ldmatrix.sync.aligned.m8n8.x4.trans.shared.b16 {%0,%1,%2,%3}, [%4];" \
                 : "=r"(r0), "=r"(r1), "=r"(r2), "=r"(r3) : "r"(addr))

#define MMAF16(d, a, b) \
    asm volatile("mma.sync.aligned.m16n8k16.row.col.f32.f16.f16.f32 " \
                 "{%0,%1,%2,%3}, {%4,%5,%6,%7}, {%8,%9}, {%0,%1,%2,%3};" \
                 : "+f"((d)[0]), "+f"((d)[1]), "+f"((d)[2]), "+f"((d)[3]) \
                 : "r"((a)[0]), "r"((a)[1]), "r"((a)[2]), "r"((a)[3]), \
                   "r"((b)[0]), "r"((b)[1]))

__device__ __forceinline__ uint32_t packh2f(float a, float b) {
    __half2 t = __floats2half2_rn(a, b);
    return *(uint32_t*)&t;
}

// ---------------------------------------------------------------------------
// Fused convert: x and all 4 weights -> fp16.  blockIdx.y: 0 -> x, 1..4 -> W.
// ---------------------------------------------------------------------------
__global__ __launch_bounds__(256) void split_all_kernel(
    const float* __restrict__ x,  const float* __restrict__ Wq,
    const float* __restrict__ Wk, const float* __restrict__ Wv,
    const float* __restrict__ Wo,
    __half* __restrict__ x16, __half* __restrict__ w16,
    int xn4, int wn4)
{
    const int y = blockIdx.y;
    const float* in;
    __half* h16;
    int n4;
    if (y == 0) { in = x; h16 = x16; n4 = xn4; }
    else {
        const float* ws[4] = {Wq, Wk, Wv, Wo};
        in = ws[y - 1];
        h16 = w16 + (size_t)(y - 1) * DD * DD;
        n4 = wn4;
    }
    int i = blockIdx.x * blockDim.x + threadIdx.x;
    if (i >= n4) return;
    float4 v = ((const float4*)in)[i];
    ((uint32_t*)h16)[2 * i + 0] = packh2f(v.x, v.y);
    ((uint32_t*)h16)[2 * i + 1] = packh2f(v.z, v.w);
}

// ---------------------------------------------------------------------------
// fp16 single-term GEMM (Round-15 proven config, unchanged):
// 512 threads / 16 warps, warp tile 32x32, CTA 128x128.
// BK=64 (4 k16 steps per chunk), 4-stage cp.async, one barrier per chunk.
// SMEM row: 128B data + 16B pad (pitch 144).
// ---------------------------------------------------------------------------
#define TPITCHB  144
#define TILEB    (128 * TPITCHB)       // 18432
#define STAGEB   (2 * TILEB)           // 36864 (X tile + W tile)
#define NSTAGE   4
#define GSMEM_TOTAL (NSTAGE * STAGEB)  // 147456
#define NCHUNK   (KK / 64)             // 32

__global__ __launch_bounds__(512, 1) void gemm_f16(
    const __half* __restrict__ X16, const __half* __restrict__ W16Base,
    float* __restrict__ Yf,
    __half* __restrict__ Y0, __half* __restrict__ Y1, __half* __restrict__ Y2,
    int qkv)
{
    extern __shared__ char smem[];
    const uint32_t sb = smem_to_u32(smem);

    const int tid  = threadIdx.x;
    const int wid  = tid >> 5;
    const int lane = tid & 31;
    const int wm   = wid >> 2;    // 0..3
    const int wn   = wid & 3;     // 0..3
    const int m0   = blockIdx.y * 128;
    const int n0   = blockIdx.x * 128;
    const int z    = blockIdx.z;

    const __half* W16 = W16Base + (size_t)z * DD * DD;

    const int ltile = tid >> 8;
    const int lwi   = tid & 255;
    const __half* gbase = (ltile == 0) ? X16 : W16;
    const int rowoff = (ltile == 0) ? m0 : n0;
    const uint32_t stile = sb + ltile * TILEB;

    auto load_stage = [&](int chunk, int s) {
        const int k0 = chunk * 64;
        const uint32_t sstage = stile + s * STAGEB;
        #pragma unroll
        for (int i = 0; i < 4; i++) {
            int idx = lwi + i * 256;
            int row = idx >> 3;
            int seg = idx & 7;
            cp_async16(sstage + (uint32_t)(row * TPITCHB + seg * 16),
                       gbase + (size_t)(rowoff + row) * KK + k0 + seg * 8);
        }
    };

    const uint32_t aoff = (uint32_t)((wm * 32 + (lane & 15)) * TPITCHB + (lane >> 4) * 16);
    const uint32_t boff = (uint32_t)((wn * 32 + ((lane >> 4) << 3) + (lane & 7)) * TPITCHB
                                     + ((lane >> 3) & 1) * 16);

    float acc[2][4][4];
    #pragma unroll
    for (int mt = 0; mt < 2; mt++)
        #pragma unroll
        for (int nt = 0; nt < 4; nt++)
            #pragma unroll
            for (int r = 0; r < 4; r++) acc[mt][nt][r] = 0.f;

    load_stage(0, 0); CP_COMMIT();
    load_stage(1, 1); CP_COMMIT();
    load_stage(2, 2); CP_COMMIT();

    for (int t = 0; t < NCHUNK; t++) {
        const int s = t & 3;
        CP_WAIT2();
        __syncthreads();

        if (t + 3 < NCHUNK) load_stage(t + 3, (t + 3) & 3);
        CP_COMMIT();

        const uint32_t stA = sb + s * STAGEB;
        const uint32_t stB = stA + TILEB;

        #pragma unroll
        for (int ks = 0; ks < 4; ks++) {
            uint32_t ah[2][4], bh[4][2];
            #pragma unroll
            for (int mt = 0; mt < 2; mt++)
                LDSM4(ah[mt][0], ah[mt][1], ah[mt][2], ah[mt][3],
                      stA + aoff + mt * (16 * TPITCHB) + ks * 32);
            #pragma unroll
            for (int bt = 0; bt < 2; bt++) {
                uint32_t r0, r1, r2, r3;
                LDSM4(r0, r1, r2, r3, stB + boff + bt * (16 * TPITCHB) + ks * 32);
                bh[bt * 2][0] = r0; bh[bt * 2][1] = r1;
                bh[bt * 2 + 1][0] = r2; bh[bt * 2 + 1][1] = r3;
            }
            #pragma unroll
            for (int mt = 0; mt < 2; mt++)
                #pragma unroll
                for (int nt = 0; nt < 4; nt++)
                    MMAF16(acc[mt][nt], ah[mt], bh[nt]);
        }
    }

    // ---- epilogue ----
    __half* Yh = (z == 0) ? Y0 : (z == 1) ? Y1 : Y2;
    #pragma unroll
    for (int mt = 0; mt < 2; mt++) {
        const int mrow = m0 + wm * 32 + mt * 16 + (lane >> 2);
        #pragma unroll
        for (int nt = 0; nt < 4; nt++) {
            const int ncl = wn * 32 + nt * 8 + (lane & 3) * 2;
            float a0 = acc[mt][nt][0], a1 = acc[mt][nt][1];
            float a2 = acc[mt][nt][2], a3 = acc[mt][nt][3];
            if (qkv) {
                const int b = mrow >> 11;
                const int srow = mrow & 2047;
                const int h = n0 >> 7;
                size_t idx0 = (((size_t)(b * HH + h) * SS) + srow) * HD + ncl;
                size_t idx1 = idx0 + (size_t)8 * HD;
                *(uint32_t*)(Yh + idx0) = packh2f(a0, a1);
                *(uint32_t*)(Yh + idx1) = packh2f(a2, a3);
            } else {
                float* basep = Yf + (size_t)mrow * DD + n0 + ncl;
                *(float2*)basep = make_float2(a0, a1);
                *(float2*)(basep + (size_t)8 * DD) = make_float2(a2, a3);
            }
        }
    }
}

// ---------------------------------------------------------------------------
// fp16 flash attention (Round-15 + Q-fragment hoist): BQ=128, 8 warps,
// warp-local softmax, P in registers. KV stage = 128 rows (K0|V0|K1|V1),
// two 64-row halves per barrier pair. Q fragments loaded ONCE into
// registers (32 regs) before the kv loop — no Q LDSM in the mainloop.
// ---------------------------------------------------------------------------
#define APITCH    272
#define AQ_TILE   (128 * APITCH)     // 34816
#define AKV_TILE  (64 * APITCH)      // 17408
#define ASTAGE2   (4 * AKV_TILE)     // 69632 (K0,V0,K1,V1)
#define AOFF_STAGE AQ_TILE
#define ATT_SMEM  (AQ_TILE + 2 * ASTAGE2)   // 174080
#define NKV2      (SS / 128)         // 16

__global__ __launch_bounds__(256, 1) void attn_f16(
    const __half* __restrict__ Q16, const __half* __restrict__ K16,
    const __half* __restrict__ V16, __half* __restrict__ A16)
{
    extern __shared__ char smem[];
    const uint32_t sb = smem_to_u32(smem);

    const int tid  = threadIdx.x;
    const int wid  = tid >> 5;     // 0..7: q-row band of 16
    const int lane = tid & 31;
    const int q0   = blockIdx.x * 128;
    const int bh   = blockIdx.y;
    const size_t bhoff = (size_t)bh * SS * HD;

    // ---- load Q: 128 rows x 128 cols fp16 ----
    {
        const __half* qp = Q16 + bhoff + (size_t)q0 * HD;
        for (int i = tid; i < 128 * 16; i += 256) {
            int r = i >> 4, c = i & 15;
            *(uint4*)(smem + r * APITCH + c * 16) =
                *(const uint4*)(qp + (size_t)r * HD + c * 8);
        }
    }

    const __half* kvbase[2] = {K16 + bhoff, V16 + bhoff};
    // Stage layout: tile tau 0..3 = K_half0, V_half0, K_half1, V_half1
    auto load_kv = [&](int chunk, int s) {
        const uint32_t sstage = sb + AOFF_STAGE + s * ASTAGE2;
        #pragma unroll
        for (int t = 0; t < 16; t++) {
            int tau  = t >> 2;
            int sub  = t & 3;
            int r    = sub * 16 + (tid >> 4);   // 0..63
            int c    = tid & 15;
            int kind = tau & 1;                 // 0:K 1:V
            int half = tau >> 1;                // 0,1
            cp_async16(sstage + tau * AKV_TILE + r * APITCH + c * 16,
                       kvbase[kind] + (size_t)(chunk * 128 + half * 64 + r) * HD + c * 8);
        }
    };

    const uint32_t qBase = sb + (wid * 16 + (lane & 15)) * APITCH + (lane >> 4) * 16;
    const uint32_t kFragOff = (uint32_t)((((lane >> 4) << 3) + (lane & 7)) * APITCH
                                         + ((lane >> 3) & 1) * 16);
    const int vRow = ((lane >> 3) & 1) * 8 + (lane & 7);
    const uint32_t vColBase = (uint32_t)((lane >> 4) * 16);

    float of[16][4];
    #pragma unroll
    for (int i = 0; i < 16; i++)
        #pragma unroll
        for (int j = 0; j < 4; j++) of[i][j] = 0.f;
    float m0 = -1e30f, m1 = -1e30f, l0 = 0.f, l1 = 0.f;

    const float sm_scale = 0.08838834764831843f;  // 1/sqrt(128)

    load_kv(0, 0); CP_COMMIT();
    load_kv(1, 1); CP_COMMIT();

    // ---- hoist Q fragments into registers (invariant over kv loop) ----
    __syncthreads();   // Q tile fully in SMEM (kv stage 0 may still be in flight)
    uint32_t qfrag[8][4];
    #pragma unroll
    for (int ks = 0; ks < 8; ks++)
        LDSM4(qfrag[ks][0], qfrag[ks][1], qfrag[ks][2], qfrag[ks][3],
              qBase + ks * 32);

    for (int t = 0; t < NKV2; t++) {
        const int s = t & 1;
        CP_WAIT1();
        __syncthreads();   // stage t resident

        const uint32_t sstage = sb + AOFF_STAGE + s * ASTAGE2;

        #pragma unroll
        for (int h2 = 0; h2 < 2; h2++) {
            const uint32_t sK = sstage + (2 * h2) * AKV_TILE;
            const uint32_t sV = sK + AKV_TILE;

            // ---- S = Q K^T over 64 kv rows (8 n8 tiles) ----
            float sf[8][4];
            #pragma unroll
            for (int nt = 0; nt < 8; nt++)
                #pragma unroll
                for (int j = 0; j < 4; j++) sf[nt][j] = 0.f;

            #pragma unroll
            for (int ks = 0; ks < 8; ks++) {
                uint32_t kh[8][2];
                #pragma unroll
                for (int nk = 0; nk < 4; nk++) {
                    uint32_t r0, r1, r2, r3;
                    LDSM4(r0, r1, r2, r3, sK + nk * (16 * APITCH) + kFragOff + ks * 32);
                    kh[nk * 2][0] = r0; kh[nk * 2][1] = r1;
                    kh[nk * 2 + 1][0] = r2; kh[nk * 2 + 1][1] = r3;
                }
                #pragma unroll
                for (int nt = 0; nt < 8; nt++)
                    MMAF16(sf[nt], qfrag[ks], kh[nt]);
            }

            // ---- warp-local online softmax ----
            #pragma unroll
            for (int nt = 0; nt < 8; nt++)
                #pragma unroll
                for (int j = 0; j < 4; j++) sf[nt][j] *= sm_scale;

            float mx0 = -1e30f, mx1 = -1e30f;
            #pragma unroll
            for (int nt = 0; nt < 8; nt++) {
                mx0 = fmaxf(mx0, fmaxf(sf[nt][0], sf[nt][1]));
                mx1 = fmaxf(mx1, fmaxf(sf[nt][2], sf[nt][3]));
            }
            mx0 = fmaxf(mx0, __shfl_xor_sync(0xffffffffu, mx0, 1));
            mx0 = fmaxf(mx0, __shfl_xor_sync(0xffffffffu, mx0, 2));
            mx1 = fmaxf(mx1, __shfl_xor_sync(0xffffffffu, mx1, 1));
            mx1 = fmaxf(mx1, __shfl_xor_sync(0xffffffffu, mx1, 2));

            const float mn0 = fmaxf(m0, mx0);
            const float mn1 = fmaxf(m1, mx1);
            const float al0 = __expf(m0 - mn0);
            const float al1 = __expf(m1 - mn1);

            float sum0 = 0.f, sum1 = 0.f;
            #pragma unroll
            for (int nt = 0; nt < 8; nt++) {
                sf[nt][0] = __expf(sf[nt][0] - mn0);
                sf[nt][1] = __expf(sf[nt][1] - mn0);
                sf[nt][2] = __expf(sf[nt][2] - mn1);
                sf[nt][3] = __expf(sf[nt][3] - mn1);
                sum0 += sf[nt][0] + sf[nt][1];
                sum1 += sf[nt][2] + sf[nt][3];
            }
            sum0 += __shfl_xor_sync(0xffffffffu, sum0, 1);
            sum0 += __shfl_xor_sync(0xffffffffu, sum0, 2);
            sum1 += __shfl_xor_sync(0xffffffffu, sum1, 1);
            sum1 += __shfl_xor_sync(0xffffffffu, sum1, 2);

            l0 = l0 * al0 + sum0;
            l1 = l1 * al1 + sum1;
            m0 = mn0; m1 = mn1;

            #pragma unroll
            for (int nt = 0; nt < 16; nt++) {
                of[nt][0] *= al0; of[nt][1] *= al0;
                of[nt][2] *= al1; of[nt][3] *= al1;
            }

            // ---- O += P V  (P fp16 from registers) ----
            #pragma unroll
            for (int ks = 0; ks < 4; ks++) {
                const int t0 = 2 * ks, t1 = 2 * ks + 1;
                uint32_t ph[4];
                ph[0] = packh2f(sf[t0][0], sf[t0][1]);
                ph[1] = packh2f(sf[t0][2], sf[t0][3]);
                ph[2] = packh2f(sf[t1][0], sf[t1][1]);
                ph[3] = packh2f(sf[t1][2], sf[t1][3]);
                const uint32_t vro = (uint32_t)((ks * 16 + vRow) * APITCH) + vColBase;
                #pragma unroll
                for (int nt4 = 0; nt4 < 8; nt4++) {
                    uint32_t r0, r1, r2, r3;
                    uint32_t vh0[2], vh1[2];
                    LDSM4T(r0, r1, r2, r3, sV + vro + nt4 * 32);
                    vh0[0] = r0; vh0[1] = r1; vh1[0] = r2; vh1[1] = r3;
                    MMAF16(of[nt4 * 2], ph, vh0);
                    MMAF16(of[nt4 * 2 + 1], ph, vh1);
                }
            }
        }

        __syncthreads();   // all reads of stage s done before overwrite
        if (t + 2 < NKV2) { load_kv(t + 2, s); CP_COMMIT(); }
    }

    // ---- epilogue: O/l -> fp16 at [b, s, d] ----
    const int b = bh >> 4;
    const int h = bh & 15;
    const float inv0 = 1.0f / l0;
    const float inv1 = 1.0f / l1;
    const int s0 = q0 + wid * 16 + (lane >> 2);
    #pragma unroll
    for (int nt = 0; nt < 16; nt++) {
        const int d = h * 128 + nt * 8 + (lane & 3) * 2;
        size_t idx0 = ((size_t)(b * SS + s0)) * DD + d;
        size_t idx1 = idx0 + (size_t)8 * DD;
        *(uint32_t*)(A16 + idx0) = packh2f(of[nt][0] * inv0, of[nt][1] * inv0);
        *(uint32_t*)(A16 + idx1) = packh2f(of[nt][2] * inv1, of[nt][3] * inv1);
    }
}

// ---------------------------------------------------------------------------
extern "C" void kernel_launch(void* const* d_in, const int* in_sizes, int n_in,
                              void* d_out, int out_size)
{
    const float* x  = (const float*)d_in[0];
    const float* Wq = (const float*)d_in[1];
    const float* Wk = (const float*)d_in[2];
    const float* Wv = (const float*)d_in[3];
    const float* Wo = (const float*)d_in[4];

    __half *x16, *w16, *q16, *k16, *v16, *a16;
    cudaGetSymbolAddress((void**)&x16, g_x16);
    cudaGetSymbolAddress((void**)&w16, g_w16);
    cudaGetSymbolAddress((void**)&q16, g_q16);
    cudaGetSymbolAddress((void**)&k16, g_k16);
    cudaGetSymbolAddress((void**)&v16, g_v16);
    cudaGetSymbolAddress((void**)&a16, g_a16);

    cudaFuncSetAttribute(gemm_f16, cudaFuncAttributeMaxDynamicSharedMemorySize,
                         GSMEM_TOTAL);
    cudaFuncSetAttribute(attn_f16, cudaFuncAttributeMaxDynamicSharedMemorySize,
                         ATT_SMEM);

    const int xn4 = (int)((size_t)MTOT * DD / 4);
    const int wn4 = (int)((size_t)DD * DD / 4);

    split_all_kernel<<<dim3((xn4 + 255) / 256, 5), 256>>>(
        x, Wq, Wk, Wv, Wo, x16, w16, xn4, wn4);

    dim3 gqkv(DD / 128, MTOT / 128, 3);
    gemm_f16<<<gqkv, 512, GSMEM_TOTAL>>>(x16, w16, nullptr,
                                         q16, k16, v16, 1);

    attn_f16<<<dim3(SS / 128, Bb * HH), 256, ATT_SMEM>>>(q16, k16, v16, a16);

    dim3 go(DD / 128, MTOT / 128, 1);
    gemm_f16<<<go, 512, GSMEM_TOTAL>>>(a16, w16 + (size_t)3 * DD * DD,
                                       (float*)d_out,
                                       nullptr, nullptr, nullptr, 0);
}